// round 11
// baseline (speedup 1.0000x reference)
#include <cuda_runtime.h>
#include <cstdint>

#define Bsz 8
#define Nn 5000
#define NODES 12             // nodes per block: 6 warps * 2 nodes
#define THREADS 192

// smem layout in 4B units
#define U_W    0             // 5 * 2048 (five weights, fp16 frag layout)
#define U_BIAS 10240         // 320 f32
#define U_A0   10560         // slab0: 6 warps * 32 rows * 32u = 6144
#define U_A1   16704         // slab1: 6144
#define U_TOT  22848         // 91,392 B -> 2 CTAs/SM

typedef unsigned long long u64;

// ---------------- helpers ----------------
__device__ __forceinline__ unsigned ph2(float x, float y) {   // lo = x, hi = y
    unsigned r;
    asm("cvt.rn.f16x2.f32 %0, %1, %2;" : "=r"(r) : "f"(y), "f"(x));
    return r;
}
__device__ __forceinline__ void ld_pair(const unsigned* p, unsigned& lo, unsigned& hi) {
    const u64 v = *(const u64*)p;
    lo = (unsigned)v; hi = (unsigned)(v >> 32);
}
__device__ __forceinline__ int posj(int jj) { return ((jj & 3) << 1) | (jj >> 2); }

__device__ __forceinline__ void mma16(float d[4], const unsigned a[4],
                                      unsigned b0, unsigned b1) {
    asm volatile(
        "mma.sync.aligned.m16n8k16.row.col.f32.f16.f16.f32 "
        "{%0,%1,%2,%3}, {%4,%5,%6,%7}, {%8,%9}, {%0,%1,%2,%3};"
        : "+f"(d[0]), "+f"(d[1]), "+f"(d[2]), "+f"(d[3])
        : "r"(a[0]), "r"(a[1]), "r"(a[2]), "r"(a[3]), "r"(b0), "r"(b1));
}
__device__ __forceinline__ void mma8(float d[4], unsigned a0, unsigned a1, unsigned b0) {
    asm volatile(
        "mma.sync.aligned.m16n8k8.row.col.f32.f16.f16.f32 "
        "{%0,%1,%2,%3}, {%4,%5}, {%6}, {%0,%1,%2,%3};"
        : "+f"(d[0]), "+f"(d[1]), "+f"(d[2]), "+f"(d[3])
        : "r"(a0), "r"(a1), "r"(b0));
}

// ---------------- kernel ----------------
__global__ void __launch_bounds__(THREADS, 2)
fused_reg2_kernel(const float* __restrict__ X,
                  const float* __restrict__ STE_P,
                  const float* __restrict__ STE_Q,
                  const float* __restrict__ W21, const float* __restrict__ b21,
                  const float* __restrict__ W22, const float* __restrict__ b22,
                  const float* __restrict__ W23, const float* __restrict__ b23,
                  const float* __restrict__ W24, const float* __restrict__ b24,
                  const float* __restrict__ W25, const float* __restrict__ b25,
                  float* __restrict__ Out)
{
    extern __shared__ unsigned sm[];
    unsigned* sW    = sm + U_W;
    float*    sBias = (float*)(sm + U_BIAS);
    unsigned* sA0   = sm + U_A0;
    unsigned* sA1   = sm + U_A1;

    const int tid  = threadIdx.x;
    const int w    = tid >> 5;
    const int lane = tid & 31;
    const int gid  = lane >> 2;
    const int tig  = lane & 3;
    const int g3   = gid & 3;
    const int b    = blockIdx.y;
    const int n0   = blockIdx.x * NODES;
    const int nodeA = n0 + 2 * w;
    const bool val0 = (nodeA < Nn);
    const bool val1 = (nodeA + 1 < Nn);
    const int rbase = 32 * w;

    // staging indices (node 0; node 1 = +64 global floats, +512 smem units)
    int gof[6], sap[6];
#pragma unroll
    for (int i = 0; i < 6; i++) {
        const int idx = lane + 32 * i;
        const int row = idx >> 4, c4 = idx & 15;
        gof[i] = ((b * 12 + row) * Nn + nodeA) * 64 + c4 * 4;
        sap[i] = (rbase + row) * 32 + (((c4 >> 2) ^ (row & 3)) << 3)
                 + posj((2 * c4) & 7);
    }

    if (tid < 64) {
        sBias[tid]       = b21[tid];
        sBias[64 + tid]  = b22[tid];
        sBias[128 + tid] = b23[tid];
        sBias[192 + tid] = b24[tid];
        sBias[256 + tid] = b25[tid];
    }

    // stage all five weights (fp16 frag layout)
    {
        const float* Ws[5] = { W21, W22, W23, W24, W25 };
#pragma unroll
        for (int s = 0; s < 5; s++) {
            unsigned* dw = sW + s * 2048;
#pragma unroll
            for (int it = 0; it < 6; it++) {
                const int idx = tid + it * THREADS;
                if (idx < 1024) {
                    const int n = idx >> 4, c4 = idx & 15;
                    const float4 v = *(const float4*)(Ws[s] + n * 64 + c4 * 4);
                    const int a0 = n * 32 + (((c4 >> 2) ^ (n & 3)) << 3)
                                   + posj((2 * c4) & 7);
                    dw[a0]     = ph2(v.x, v.y);
                    dw[a0 + 2] = ph2(v.z, v.w);
                }
            }
        }
    }

    // zero pad rows 12-15 of both slots in both slabs
    {
        const uint4 z4 = make_uint4(0, 0, 0, 0);
#pragma unroll
        for (int nn = 0; nn < 2; nn++) {
            ((uint4*)(sA0 + (rbase + 16 * nn + 12) * 32))[lane] = z4;
            ((uint4*)(sA1 + (rbase + 16 * nn + 12) * 32))[lane] = z4;
        }
    }

    // stage STE_Q -> slab0 (pre-sync, direct)
#pragma unroll
    for (int nn = 0; nn < 2; nn++) {
        if (nn ? val1 : val0) {
#pragma unroll
            for (int i = 0; i < 6; i++) {
                const float4 v = *(const float4*)(STE_Q + gof[i] + nn * 64);
                sA0[sap[i] + nn * 512]     = ph2(v.x, v.y);
                sA0[sap[i] + nn * 512 + 2] = ph2(v.z, v.w);
            }
        }
    }
    __syncthreads();                                    // the ONLY block sync

    uint2 hx[12];
#define PREFETCH2(src)                                                      \
    {                                                                       \
        _Pragma("unroll")                                                   \
        for (int nn = 0; nn < 2; nn++) {                                    \
            if (nn ? val1 : val0) {                                         \
                _Pragma("unroll")                                           \
                for (int i = 0; i < 6; i++) {                               \
                    const float4 v = *(const float4*)((src) + gof[i] + nn * 64); \
                    hx[6 * nn + i].x = ph2(v.x, v.y);                       \
                    hx[6 * nn + i].y = ph2(v.z, v.w);                       \
                }                                                           \
            }                                                               \
        }                                                                   \
    }

#define STS2(slab)                                                          \
    {                                                                       \
        _Pragma("unroll")                                                   \
        for (int nn = 0; nn < 2; nn++) {                                    \
            if (nn ? val1 : val0) {                                         \
                _Pragma("unroll")                                           \
                for (int i = 0; i < 6; i++) {                               \
                    (slab)[sap[i] + nn * 512]     = hx[6 * nn + i].x;       \
                    (slab)[sap[i] + nn * 512 + 2] = hx[6 * nn + i].y;       \
                }                                                           \
            }                                                               \
        }                                                                   \
    }

#define LOAD_A2(slab)                                                       \
    {                                                                       \
        _Pragma("unroll")                                                   \
        for (int kc = 0; kc < 4; kc++) {                                    \
            const int off = ((kc ^ g3) << 3) + 2 * tig;                     \
            ld_pair((slab) + (rbase + gid) * 32 + off,      a0f[kc][0], a0f[kc][2]); \
            ld_pair((slab) + (rbase + 8 + gid) * 32 + off,  a0f[kc][1], a0f[kc][3]); \
            ld_pair((slab) + (rbase + 16 + gid) * 32 + off, a1f[kc][0], a1f[kc][2]); \
            ld_pair((slab) + (rbase + 24 + gid) * 32 + off, a1f[kc][1], a1f[kc][3]); \
        }                                                                   \
    }

// GEMM for both nodes sharing weight b-frags; pack bias+relu(*mult)
#define GEMM_PACK2(wsel, boff, mult, dst0, dst1)                            \
    {                                                                       \
        _Pragma("unroll")                                                   \
        for (int nt = 0; nt < 8; nt++) {                                    \
            float dd0[4] = {0.f, 0.f, 0.f, 0.f};                            \
            float dd1[4] = {0.f, 0.f, 0.f, 0.f};                            \
            const unsigned* wr = sW + (wsel) * 2048 + (nt * 8 + gid) * 32;  \
            _Pragma("unroll")                                               \
            for (int kc = 0; kc < 4; kc++) {                                \
                unsigned b0, b1;                                            \
                ld_pair(wr + ((kc ^ g3) << 3) + 2 * tig, b0, b1);           \
                mma16(dd0, a0f[kc], b0, b1);                                \
                mma16(dd1, a1f[kc], b0, b1);                                \
            }                                                               \
            const float2 bc = *(const float2*)(sBias + (boff) + nt * 8 + 2 * tig); \
            (dst0)[nt][0] = ph2(fmaxf(dd0[0] + bc.x, 0.f) * (mult),         \
                                fmaxf(dd0[1] + bc.y, 0.f) * (mult));        \
            (dst0)[nt][1] = ph2(fmaxf(dd0[2] + bc.x, 0.f) * (mult),         \
                                fmaxf(dd0[3] + bc.y, 0.f) * (mult));        \
            (dst1)[nt][0] = ph2(fmaxf(dd1[0] + bc.x, 0.f) * (mult),         \
                                fmaxf(dd1[1] + bc.y, 0.f) * (mult));        \
            (dst1)[nt][1] = ph2(fmaxf(dd1[2] + bc.x, 0.f) * (mult),         \
                                fmaxf(dd1[3] + bc.y, 0.f) * (mult));        \
        }                                                                   \
    }

// GEMM with A from packed reg-pairs for both nodes, shared weight b-frags
#define GEMM_REG2(wsel, s0, s1, nt, dd0, dd1)                               \
    {                                                                       \
        const unsigned* wr = sW + (wsel) * 2048 + ((nt) * 8 + gid) * 32;    \
        _Pragma("unroll")                                                   \
        for (int kc = 0; kc < 4; kc++) {                                    \
            unsigned b0, b1;                                                \
            ld_pair(wr + ((kc ^ g3) << 3) + 2 * tig, b0, b1);               \
            unsigned aR0[4] = { (s0)[2 * kc][0], (s0)[2 * kc][1],           \
                                (s0)[2 * kc + 1][0], (s0)[2 * kc + 1][1] }; \
            mma16(dd0, aR0, b0, b1);                                        \
            unsigned aR1[4] = { (s1)[2 * kc][0], (s1)[2 * kc][1],           \
                                (s1)[2 * kc + 1][0], (s1)[2 * kc + 1][1] }; \
            mma16(dd1, aR1, b0, b1);                                        \
        }                                                                   \
    }

    unsigned a0f[4][4], a1f[4][4];
    unsigned qa2[2][8][2], kb2[2][8][2], vb2[2][8][2];
    const float scale = 0.35355339059327373f;           // 1/sqrt(8), folded into Q

    // ---- phase A: Q (scaled) -> qa2 ; stage STE_P -> slab1 ----
    PREFETCH2(STE_P);
    LOAD_A2(sA0);
    GEMM_PACK2(0, 0, scale, qa2[0], qa2[1]);
    STS2(sA1);

    // ---- phase B: K -> kb2 ; stage X -> slab0 ----
    PREFETCH2(X);
    LOAD_A2(sA1);
    GEMM_PACK2(1, 64, 1.f, kb2[0], kb2[1]);
    __syncwarp();                                       // X STS after slab0 A-frag reads? (A-frags from slab1; slab0 write ok)
    STS2(sA0);
    __syncwarp();                                       // X visible before phase C reads

    // ---- phase C (transposed): Vt = W23 * X^T -> vb2 (O-MMA B-frags) ----
#pragma unroll
    for (int mt = 0; mt < 4; mt++) {
        unsigned wa[4][4];
#pragma unroll
        for (int kc = 0; kc < 4; kc++) {
            const int off = ((kc ^ g3) << 3) + 2 * tig;
            ld_pair(sW + 2 * 2048 + (16 * mt + gid) * 32 + off, wa[kc][0], wa[kc][2]);
            ld_pair(sW + 2 * 2048 + (16 * mt + 8 + gid) * 32 + off, wa[kc][1], wa[kc][3]);
        }
        const float bj0 = sBias[128 + 16 * mt + gid];
        const float bj1 = sBias[128 + 16 * mt + 8 + gid];
#pragma unroll
        for (int nn = 0; nn < 2; nn++) {
            float d0[4] = {0.f, 0.f, 0.f, 0.f};
            float d1[4] = {0.f, 0.f, 0.f, 0.f};
            const unsigned* base0 = sA0 + (rbase + 16 * nn + gid) * 32;
            const unsigned* base1 = sA0 + (rbase + 16 * nn + 8 + gid) * 32;
#pragma unroll
            for (int kc = 0; kc < 4; kc++) {
                const int off = ((kc ^ g3) << 3) + 2 * tig;
                unsigned b0, b1;
                ld_pair(base0 + off, b0, b1);
                mma16(d0, wa[kc], b0, b1);
                ld_pair(base1 + off, b0, b1);
                mma16(d1, wa[kc], b0, b1);
            }
            vb2[nn][2 * mt][0]     = ph2(fmaxf(d0[0] + bj0, 0.f), fmaxf(d0[1] + bj0, 0.f));
            vb2[nn][2 * mt][1]     = ph2(fmaxf(d1[0] + bj0, 0.f), fmaxf(d1[1] + bj0, 0.f));
            vb2[nn][2 * mt + 1][0] = ph2(fmaxf(d0[2] + bj1, 0.f), fmaxf(d0[3] + bj1, 0.f));
            vb2[nn][2 * mt + 1][1] = ph2(fmaxf(d1[2] + bj1, 0.f), fmaxf(d1[3] + bj1, 0.f));
        }
    }

    // ---- attention per node: all in registers ----
    unsigned oa2[2][8][2];
#pragma unroll
    for (int nn = 0; nn < 2; nn++) {
#pragma unroll
        for (int h = 0; h < 8; h++) {
            float s1[4] = {0.f, 0.f, 0.f, 0.f};
            float s2[4] = {0.f, 0.f, 0.f, 0.f};
            mma8(s1, qa2[nn][h][0], qa2[nn][h][1], kb2[nn][h][0]);   // p = 0..7
            mma8(s2, qa2[nn][h][0], qa2[nn][h][1], kb2[nn][h][1]);   // p = 8..15
            const float e10 = __expf(s1[0] - 8.f), e11 = __expf(s1[1] - 8.f);
            const float e12 = __expf(s1[2] - 8.f), e13 = __expf(s1[3] - 8.f);
            float e20 = 0.f, e21 = 0.f, e22 = 0.f, e23 = 0.f;
            if (tig < 2) {                                           // p = 8+2tig < 12
                e20 = __expf(s2[0] - 8.f); e21 = __expf(s2[1] - 8.f);
                e22 = __expf(s2[2] - 8.f); e23 = __expf(s2[3] - 8.f);
            }
            float sumA = e10 + e11 + e20 + e21;
            float sumB = e12 + e13 + e22 + e23;
            sumA += __shfl_xor_sync(0xffffffffu, sumA, 1);
            sumA += __shfl_xor_sync(0xffffffffu, sumA, 2);
            sumB += __shfl_xor_sync(0xffffffffu, sumB, 1);
            sumB += __shfl_xor_sync(0xffffffffu, sumB, 2);
            const float invA = __fdividef(1.f, sumA);
            const float invB = __fdividef(1.f, sumB);
            unsigned pa[4];
            pa[0] = ph2(e10 * invA, e11 * invA);
            pa[1] = ph2(e12 * invB, e13 * invB);
            pa[2] = ph2(e20 * invA, e21 * invA);
            pa[3] = ph2(e22 * invB, e23 * invB);
            float ov[4] = {0.f, 0.f, 0.f, 0.f};
            mma16(ov, pa, vb2[nn][h][0], vb2[nn][h][1]);
            oa2[nn][h][0] = ph2(ov[0], ov[1]);
            oa2[nn][h][1] = ph2(ov[2], ov[3]);
        }
    }

    // ---- phase D: H = relu(attn @ W24^T + b24) -> ha2 ----
    unsigned ha2[2][8][2];
#pragma unroll
    for (int nt = 0; nt < 8; nt++) {
        float dd0[4] = {0.f, 0.f, 0.f, 0.f};
        float dd1[4] = {0.f, 0.f, 0.f, 0.f};
        GEMM_REG2(3, oa2[0], oa2[1], nt, dd0, dd1);
        const float2 bc = *(const float2*)(sBias + 192 + nt * 8 + 2 * tig);
        ha2[0][nt][0] = ph2(fmaxf(dd0[0] + bc.x, 0.f), fmaxf(dd0[1] + bc.y, 0.f));
        ha2[0][nt][1] = ph2(fmaxf(dd0[2] + bc.x, 0.f), fmaxf(dd0[3] + bc.y, 0.f));
        ha2[1][nt][0] = ph2(fmaxf(dd1[0] + bc.x, 0.f), fmaxf(dd1[1] + bc.y, 0.f));
        ha2[1][nt][1] = ph2(fmaxf(dd1[2] + bc.x, 0.f), fmaxf(dd1[3] + bc.y, 0.f));
    }

    // ---- phase E: out = H @ W25^T + b25 -> global ----
    {
        float* oA0 = Out + ((size_t)(b * 12 + gid) * Nn + nodeA) * 64;
        float* oA1 = Out + ((size_t)(b * 12 + gid + 8) * Nn + nodeA) * 64;
#pragma unroll
        for (int nt = 0; nt < 8; nt++) {
            float dd0[4] = {0.f, 0.f, 0.f, 0.f};
            float dd1[4] = {0.f, 0.f, 0.f, 0.f};
            GEMM_REG2(4, ha2[0], ha2[1], nt, dd0, dd1);
            const float2 bc = *(const float2*)(sBias + 256 + nt * 8 + 2 * tig);
            const int c = nt * 8 + 2 * tig;
            if (val0) {
                *(float2*)(oA0 + c) = make_float2(dd0[0] + bc.x, dd0[1] + bc.y);
                if (gid < 4)
                    *(float2*)(oA1 + c) = make_float2(dd0[2] + bc.x, dd0[3] + bc.y);
            }
            if (val1) {
                *(float2*)(oA0 + 64 + c) = make_float2(dd1[0] + bc.x, dd1[1] + bc.y);
                if (gid < 4)
                    *(float2*)(oA1 + 64 + c) = make_float2(dd1[2] + bc.x, dd1[3] + bc.y);
            }
        }
    }
#undef PREFETCH2
#undef STS2
#undef LOAD_A2
#undef GEMM_PACK2
#undef GEMM_REG2
}

extern "C" void kernel_launch(void* const* d_in, const int* in_sizes, int n_in,
                              void* d_out, int out_size)
{
    const float* X     = (const float*)d_in[0];
    const float* STE_P = (const float*)d_in[1];
    const float* STE_Q = (const float*)d_in[2];
    const float* W21   = (const float*)d_in[3];
    const float* b21   = (const float*)d_in[4];
    const float* W22   = (const float*)d_in[5];
    const float* b22   = (const float*)d_in[6];
    const float* W23   = (const float*)d_in[7];
    const float* b23   = (const float*)d_in[8];
    const float* W24   = (const float*)d_in[9];
    const float* b24   = (const float*)d_in[10];
    const float* W25   = (const float*)d_in[11];
    const float* b25   = (const float*)d_in[12];
    float* Out = (float*)d_out;

    const size_t smem_bytes = (size_t)U_TOT * 4;        // 91,392 B -> 2 CTAs/SM

    cudaFuncSetAttribute(fused_reg2_kernel,
                         cudaFuncAttributeMaxDynamicSharedMemorySize,
                         (int)smem_bytes);

    dim3 grid((Nn + NODES - 1) / NODES, Bsz);           // (417, 8)
    fused_reg2_kernel<<<grid, THREADS, smem_bytes>>>(
        X, STE_P, STE_Q,
        W21, b21, W22, b22, W23, b23, W24, b24, W25, b25,
        Out);
}

// round 12
// speedup vs baseline: 1.1414x; 1.1414x over previous
#include <cuda_runtime.h>
#include <cstdint>

#define Bsz 8
#define Nn 5000
#define NG 5                 // node-groups per block
#define NODES (6 * NG)       // 30 nodes per block
#define THREADS 192          // 6 warps, one node per warp per group

// smem layout in 4B units
#define U_W    0             // 5 * 2048 (all five weights, fp16 frag layout)
#define U_BIAS 10240         // 320 f32
#define U_A    10560         // 96*32 fp16 frag slab (input staging only)
#define U_TOT  13632         // 54,528 B -> 3 CTAs/SM

typedef unsigned long long u64;

// ---------------- helpers ----------------
__device__ __forceinline__ unsigned ph2(float x, float y) {   // lo = x, hi = y
    unsigned r;
    asm("cvt.rn.f16x2.f32 %0, %1, %2;" : "=r"(r) : "f"(y), "f"(x));
    return r;
}
__device__ __forceinline__ void ld_pair(const unsigned* p, unsigned& lo, unsigned& hi) {
    const u64 v = *(const u64*)p;
    lo = (unsigned)v; hi = (unsigned)(v >> 32);
}
__device__ __forceinline__ int posj(int jj) { return ((jj & 3) << 1) | (jj >> 2); }

__device__ __forceinline__ void mma16(float d[4], const unsigned a[4],
                                      unsigned b0, unsigned b1) {
    asm volatile(
        "mma.sync.aligned.m16n8k16.row.col.f32.f16.f16.f32 "
        "{%0,%1,%2,%3}, {%4,%5,%6,%7}, {%8,%9}, {%0,%1,%2,%3};"
        : "+f"(d[0]), "+f"(d[1]), "+f"(d[2]), "+f"(d[3])
        : "r"(a[0]), "r"(a[1]), "r"(a[2]), "r"(a[3]), "r"(b0), "r"(b1));
}
__device__ __forceinline__ void mma8(float d[4], unsigned a0, unsigned a1, unsigned b0) {
    asm volatile(
        "mma.sync.aligned.m16n8k8.row.col.f32.f16.f16.f32 "
        "{%0,%1,%2,%3}, {%4,%5}, {%6}, {%0,%1,%2,%3};"
        : "+f"(d[0]), "+f"(d[1]), "+f"(d[2]), "+f"(d[3])
        : "r"(a0), "r"(a1), "r"(b0));
}

// ---------------- kernel ----------------
__global__ void __launch_bounds__(THREADS, 3)
fused_reg_kernel(const float* __restrict__ X,
                 const float* __restrict__ STE_P,
                 const float* __restrict__ STE_Q,
                 const float* __restrict__ W21, const float* __restrict__ b21,
                 const float* __restrict__ W22, const float* __restrict__ b22,
                 const float* __restrict__ W23, const float* __restrict__ b23,
                 const float* __restrict__ W24, const float* __restrict__ b24,
                 const float* __restrict__ W25, const float* __restrict__ b25,
                 float* __restrict__ Out)
{
    extern __shared__ unsigned sm[];
    unsigned* sW = sm + U_W;
    float*    sBias = (float*)(sm + U_BIAS);
    unsigned* sA = sm + U_A;

    const int tid  = threadIdx.x;
    const int w    = tid >> 5;
    const int lane = tid & 31;
    const int gid  = lane >> 2;
    const int tig  = lane & 3;
    const int g3   = gid & 3;
    const int b    = blockIdx.y;
    const int n0   = blockIdx.x * NODES;

    const int r0 = 16 * w + gid;
    const int r1 = r0 + 8;

    // staging indices for group 0 (per group: node += 6 -> gof += 384)
    int gof[6], sap[6];
#pragma unroll
    for (int i = 0; i < 6; i++) {
        const int idx = lane + 32 * i;
        const int row = idx >> 4, c4 = idx & 15;
        gof[i] = ((b * 12 + row) * Nn + (n0 + w)) * 64 + c4 * 4;
        sap[i] = (16 * w + row) * 32 + (((c4 >> 2) ^ (row & 3)) << 3)
                 + posj((2 * c4) & 7);
    }

    if (tid < 64) {
        sBias[tid]       = b21[tid];
        sBias[64 + tid]  = b22[tid];
        sBias[128 + tid] = b23[tid];
        sBias[192 + tid] = b24[tid];
        sBias[256 + tid] = b25[tid];
    }

    // stage all five weights once (fp16 frag layout)
    {
        const float* Ws[5] = { W21, W22, W23, W24, W25 };
#pragma unroll
        for (int s = 0; s < 5; s++) {
            unsigned* dw = sW + s * 2048;
#pragma unroll
            for (int it = 0; it < 6; it++) {
                const int idx = tid + it * THREADS;
                if (idx < 1024) {
                    const int n = idx >> 4, c4 = idx & 15;
                    const float4 v = *(const float4*)(Ws[s] + n * 64 + c4 * 4);
                    const int a0 = n * 32 + (((c4 >> 2) ^ (n & 3)) << 3)
                                   + posj((2 * c4) & 7);
                    dw[a0]     = ph2(v.x, v.y);
                    dw[a0 + 2] = ph2(v.z, v.w);
                }
            }
        }
    }

    // zero pad rows 12-15 of this warp's slab (stay zero across all groups)
    ((uint4*)(sA + (16 * w + 12) * 32))[lane] = make_uint4(0, 0, 0, 0);

    uint2 hx[6];
    // stage group-0 STE_Q
    if (n0 + w < Nn) {
#pragma unroll
        for (int i = 0; i < 6; i++) {
            const float4 v = *(const float4*)(STE_Q + gof[i]);
            sA[sap[i]]     = ph2(v.x, v.y);
            sA[sap[i] + 2] = ph2(v.z, v.w);
        }
    }
    __syncthreads();                                     // the ONLY block sync

#define PREFETCH_AT(src, off)                                               \
    if (valid) {                                                            \
        _Pragma("unroll")                                                   \
        for (int i = 0; i < 6; i++) {                                       \
            const float4 v = *(const float4*)((src) + gof[i] + (off));      \
            hx[i].x = ph2(v.x, v.y);                                        \
            hx[i].y = ph2(v.z, v.w);                                        \
        }                                                                   \
    }

#define STS_IN()                                                            \
    {                                                                       \
        _Pragma("unroll")                                                   \
        for (int i = 0; i < 6; i++) {                                       \
            sA[sap[i]]     = hx[i].x;                                       \
            sA[sap[i] + 2] = hx[i].y;                                       \
        }                                                                   \
    }

#define LOAD_A(a)                                                           \
    {                                                                       \
        _Pragma("unroll")                                                   \
        for (int kc = 0; kc < 4; kc++) {                                    \
            const int off = ((kc ^ g3) << 3) + 2 * tig;                     \
            ld_pair(sA + r0 * 32 + off, (a)[kc][0], (a)[kc][2]);            \
            ld_pair(sA + r1 * 32 + off, (a)[kc][1], (a)[kc][3]);            \
        }                                                                   \
    }

#define GEMM_PACK(wsel, boff, mult, dst)                                    \
    {                                                                       \
        _Pragma("unroll")                                                   \
        for (int nt = 0; nt < 8; nt++) {                                    \
            float dd[4] = {0.f, 0.f, 0.f, 0.f};                             \
            const unsigned* wr = sW + (wsel) * 2048 + (nt * 8 + gid) * 32;  \
            _Pragma("unroll")                                               \
            for (int kc = 0; kc < 4; kc++) {                                \
                unsigned b0, b1;                                            \
                ld_pair(wr + ((kc ^ g3) << 3) + 2 * tig, b0, b1);           \
                mma16(dd, a[kc], b0, b1);                                   \
            }                                                               \
            const float2 bc = *(const float2*)(sBias + (boff) + nt * 8 + 2 * tig); \
            (dst)[nt][0] = ph2(fmaxf(dd[0] + bc.x, 0.f) * (mult),           \
                               fmaxf(dd[1] + bc.y, 0.f) * (mult));          \
            (dst)[nt][1] = ph2(fmaxf(dd[2] + bc.x, 0.f) * (mult),           \
                               fmaxf(dd[3] + bc.y, 0.f) * (mult));          \
        }                                                                   \
    }

#define GEMM_REG(wsel, src, nt, dd)                                         \
    {                                                                       \
        const unsigned* wr = sW + (wsel) * 2048 + ((nt) * 8 + gid) * 32;    \
        _Pragma("unroll")                                                   \
        for (int kc = 0; kc < 4; kc++) {                                    \
            unsigned aR[4] = { (src)[2 * kc][0], (src)[2 * kc][1],          \
                               (src)[2 * kc + 1][0], (src)[2 * kc + 1][1] };\
            unsigned b0, b1;                                                \
            ld_pair(wr + ((kc ^ g3) << 3) + 2 * tig, b0, b1);               \
            mma16(dd, aR, b0, b1);                                          \
        }                                                                   \
    }

    unsigned a[4][4];
    unsigned qa[8][2], kb[8][2], vb[8][2], oa[8][2], ha[8][2];
    const float scale = 0.35355339059327373f;            // 1/sqrt(8), folded into Q

#pragma unroll 1
    for (int g = 0; g < NG; g++) {
        const int node = n0 + g * 6 + w;
        const bool valid = (node < Nn);

        // ---- phase A: Q (scaled) -> qa regs ; stage STE_P ----
        PREFETCH_AT(STE_P, 0);
        LOAD_A(a);
        __syncwarp();
        STS_IN();
        GEMM_PACK(0, 0, scale, qa);
        __syncwarp();

        // ---- phase B: K -> kb regs ; stage X ----
        PREFETCH_AT(X, 0);
        LOAD_A(a);
        __syncwarp();
        STS_IN();
        GEMM_PACK(1, 64, 1.f, kb);
        __syncwarp();

        // ---- phase C (transposed): Vt = W23 * X^T -> vb regs ----
        // prefetch NEXT group's STE_Q during phase C MMAs
        {
            const bool validn = (node + 6 < Nn) && (g + 1 < NG);
#pragma unroll
            for (int i = 0; i < 6; i++) {
                if (validn) {
                    const float4 v = *(const float4*)(STE_Q + gof[i] + 384);
                    hx[i].x = ph2(v.x, v.y);
                    hx[i].y = ph2(v.z, v.w);
                }
            }
        }
#pragma unroll
        for (int mt = 0; mt < 4; mt++) {
            unsigned wa[4][4];
#pragma unroll
            for (int kc = 0; kc < 4; kc++) {
                const int off = ((kc ^ g3) << 3) + 2 * tig;
                ld_pair(sW + 2 * 2048 + (16 * mt + gid) * 32 + off, wa[kc][0], wa[kc][2]);
                ld_pair(sW + 2 * 2048 + (16 * mt + 8 + gid) * 32 + off, wa[kc][1], wa[kc][3]);
            }
            const float bj0 = sBias[128 + 16 * mt + gid];
            const float bj1 = sBias[128 + 16 * mt + 8 + gid];
            float d0[4] = {0.f, 0.f, 0.f, 0.f};
            float d1[4] = {0.f, 0.f, 0.f, 0.f};
#pragma unroll
            for (int kc = 0; kc < 4; kc++) {
                const int off = ((kc ^ g3) << 3) + 2 * tig;
                unsigned b0, b1;
                ld_pair(sA + r0 * 32 + off, b0, b1);
                mma16(d0, wa[kc], b0, b1);
                ld_pair(sA + r1 * 32 + off, b0, b1);
                mma16(d1, wa[kc], b0, b1);
            }
            vb[2 * mt][0]     = ph2(fmaxf(d0[0] + bj0, 0.f), fmaxf(d0[1] + bj0, 0.f));
            vb[2 * mt][1]     = ph2(fmaxf(d1[0] + bj0, 0.f), fmaxf(d1[1] + bj0, 0.f));
            vb[2 * mt + 1][0] = ph2(fmaxf(d0[2] + bj1, 0.f), fmaxf(d0[3] + bj1, 0.f));
            vb[2 * mt + 1][1] = ph2(fmaxf(d1[2] + bj1, 0.f), fmaxf(d1[3] + bj1, 0.f));
        }
        __syncwarp();                                    // slab reads done
        // stage next group's STE_Q (warp-local rows)
        if ((node + 6 < Nn) && (g + 1 < NG)) { STS_IN(); }
        __syncwarp();

        // ---- attention: per head, all in registers ----
#pragma unroll
        for (int h = 0; h < 8; h++) {
            float s1[4] = {0.f, 0.f, 0.f, 0.f};
            float s2[4] = {0.f, 0.f, 0.f, 0.f};
            mma8(s1, qa[h][0], qa[h][1], kb[h][0]);      // p = 0..7
            mma8(s2, qa[h][0], qa[h][1], kb[h][1]);      // p = 8..15 (12-15 masked)
            const float e10 = __expf(s1[0] - 8.f), e11 = __expf(s1[1] - 8.f);
            const float e12 = __expf(s1[2] - 8.f), e13 = __expf(s1[3] - 8.f);
            float e20 = 0.f, e21 = 0.f, e22 = 0.f, e23 = 0.f;
            if (tig < 2) {                               // p = 8+2tig < 12
                e20 = __expf(s2[0] - 8.f); e21 = __expf(s2[1] - 8.f);
                e22 = __expf(s2[2] - 8.f); e23 = __expf(s2[3] - 8.f);
            }
            float sumA = e10 + e11 + e20 + e21;
            float sumB = e12 + e13 + e22 + e23;
            sumA += __shfl_xor_sync(0xffffffffu, sumA, 1);
            sumA += __shfl_xor_sync(0xffffffffu, sumA, 2);
            sumB += __shfl_xor_sync(0xffffffffu, sumB, 1);
            sumB += __shfl_xor_sync(0xffffffffu, sumB, 2);
            const float invA = __fdividef(1.f, sumA);
            const float invB = __fdividef(1.f, sumB);
            unsigned pa[4];
            pa[0] = ph2(e10 * invA, e11 * invA);
            pa[1] = ph2(e12 * invB, e13 * invB);
            pa[2] = ph2(e20 * invA, e21 * invA);
            pa[3] = ph2(e22 * invB, e23 * invB);
            float ov[4] = {0.f, 0.f, 0.f, 0.f};
            mma16(ov, pa, vb[h][0], vb[h][1]);
            oa[h][0] = ph2(ov[0], ov[1]);
            oa[h][1] = ph2(ov[2], ov[3]);
        }

        // ---- phase D: H = relu(attn @ W24^T + b24) -> ha regs ----
#pragma unroll
        for (int nt = 0; nt < 8; nt++) {
            float dd[4] = {0.f, 0.f, 0.f, 0.f};
            GEMM_REG(3, oa, nt, dd);
            const float2 bc = *(const float2*)(sBias + 192 + nt * 8 + 2 * tig);
            ha[nt][0] = ph2(fmaxf(dd[0] + bc.x, 0.f), fmaxf(dd[1] + bc.y, 0.f));
            ha[nt][1] = ph2(fmaxf(dd[2] + bc.x, 0.f), fmaxf(dd[3] + bc.y, 0.f));
        }

        // ---- phase E: out = H @ W25^T + b25 -> global ----
        {
            float* o0 = Out + ((size_t)(b * 12 + gid) * Nn + node) * 64;
            float* o1 = Out + ((size_t)(b * 12 + gid + 8) * Nn + node) * 64;
#pragma unroll
            for (int nt = 0; nt < 8; nt++) {
                float dd[4] = {0.f, 0.f, 0.f, 0.f};
                GEMM_REG(4, ha, nt, dd);
                const float2 bc = *(const float2*)(sBias + 256 + nt * 8 + 2 * tig);
                if (valid) {
                    *(float2*)(o0 + nt * 8 + 2 * tig) =
                        make_float2(dd[0] + bc.x, dd[1] + bc.y);
                    if (gid < 4)
                        *(float2*)(o1 + nt * 8 + 2 * tig) =
                            make_float2(dd[2] + bc.x, dd[3] + bc.y);
                }
            }
        }

        // advance to next group (node += 6 -> +384 floats)
#pragma unroll
        for (int i = 0; i < 6; i++) gof[i] += 384;
    }
#undef PREFETCH_AT
#undef STS_IN
#undef LOAD_A
#undef GEMM_PACK
#undef GEMM_REG
}

extern "C" void kernel_launch(void* const* d_in, const int* in_sizes, int n_in,
                              void* d_out, int out_size)
{
    const float* X     = (const float*)d_in[0];
    const float* STE_P = (const float*)d_in[1];
    const float* STE_Q = (const float*)d_in[2];
    const float* W21   = (const float*)d_in[3];
    const float* b21   = (const float*)d_in[4];
    const float* W22   = (const float*)d_in[5];
    const float* b22   = (const float*)d_in[6];
    const float* W23   = (const float*)d_in[7];
    const float* b23   = (const float*)d_in[8];
    const float* W24   = (const float*)d_in[9];
    const float* b24   = (const float*)d_in[10];
    const float* W25   = (const float*)d_in[11];
    const float* b25   = (const float*)d_in[12];
    float* Out = (float*)d_out;

    const size_t smem_bytes = (size_t)U_TOT * 4;          // 54,528 B -> 3 CTAs/SM

    cudaFuncSetAttribute(fused_reg_kernel,
                         cudaFuncAttributeMaxDynamicSharedMemorySize,
                         (int)smem_bytes);

    dim3 grid((Nn + NODES - 1) / NODES, Bsz);             // (167, 8) = 1336 CTAs
    fused_reg_kernel<<<grid, THREADS, smem_bytes>>>(
        X, STE_P, STE_Q,
        W21, b21, W22, b22, W23, b23, W24, b24, W25, b25,
        Out);
}